// round 6
// baseline (speedup 1.0000x reference)
#include <cuda_runtime.h>
#include <cstdint>
#include <math.h>

#define TT   16
#define MTOT 2048
#define HH   2048
#define DIN  1024
#define DOUT 1024

#define NTHR 512
#define KCB  128              // int8 k per chunk (one 128B swizzle row)
#define TILE 64               // CTA tile 64x64
#define STAGEB 32768          // A(8KB) + 3x B plane(8KB each)

// ---------------- static device scratch ----------------
__device__ __align__(1024) int8_t g_A0 [(size_t)MTOT * DIN];
__device__ __align__(1024) int8_t g_s0 [(size_t)MTOT * HH];
__device__ __align__(1024) int8_t g_s1 [(size_t)MTOT * HH];
__device__ __align__(1024) int8_t g_W0q[(size_t)HH   * 3 * DIN];
__device__ __align__(1024) int8_t g_W1q[(size_t)HH   * 3 * HH];
__device__ __align__(1024) int8_t g_Woq[(size_t)DOUT * 3 * HH];

// ---------------- helpers ----------------
__device__ __forceinline__ uint32_t smem_u32(const void* p) {
    uint32_t a;
    asm("{ .reg .u64 t; cvta.to.shared.u64 t, %1; cvt.u32.u64 %0, t; }" : "=r"(a) : "l"(p));
    return a;
}
__device__ __forceinline__ void cp16(uint32_t dst, const void* src) {
    asm volatile("cp.async.cg.shared.global [%0], [%1], 16;" :: "r"(dst), "l"(src));
}
#define CP_COMMIT() asm volatile("cp.async.commit_group;" ::: "memory")
#define CP_WAIT(n)  asm volatile("cp.async.wait_group %0;" :: "n"(n) : "memory")
#define SWZ(off) ((off) ^ (((off) >> 3) & 0x70))

__device__ __forceinline__ void ldsm4(uint32_t& r0, uint32_t& r1, uint32_t& r2, uint32_t& r3,
                                      uint32_t addr) {
    asm volatile("ldmatrix.sync.aligned.m8n8.x4.shared.b16 {%0,%1,%2,%3}, [%4];"
                 : "=r"(r0), "=r"(r1), "=r"(r2), "=r"(r3) : "r"(addr));
}
__device__ __forceinline__ void imma(int* d, const uint32_t* a, uint32_t b0, uint32_t b1) {
    asm volatile(
        "mma.sync.aligned.m16n8k32.row.col.s32.s8.s8.s32 "
        "{%0,%1,%2,%3}, {%4,%5,%6,%7}, {%8,%9}, {%0,%1,%2,%3};"
        : "+r"(d[0]), "+r"(d[1]), "+r"(d[2]), "+r"(d[3])
        : "r"(a[0]), "r"(a[1]), "r"(a[2]), "r"(a[3]), "r"(b0), "r"(b1));
}

// exact 3-limb int8 split of round(w*2^27): l2*2^16 + l1*2^8 + l0
__device__ __forceinline__ void quant_range(const float* __restrict__ W,
                                            int8_t* __restrict__ Wq,
                                            int Nw, int K, int eblk, int nblk) {
    const int total4 = (Nw * K) >> 2;
    const int KP = 3 * K;
    for (int i4 = eblk * NTHR + threadIdx.x; i4 < total4; i4 += nblk * NTHR) {
        int idx = i4 << 2;
        int n = idx / K, k = idx - n * K;
        float4 w4 = *(const float4*)(W + idx);
        float wv[4] = {w4.x, w4.y, w4.z, w4.w};
        char l2v[4], l1v[4], l0v[4];
#pragma unroll
        for (int j = 0; j < 4; ++j) {
            long long wi = llrintf(wv[j] * 134217728.0f);   // 2^27
            int l0 = (int)((wi + 128) & 255) - 128;  wi = (wi - l0) >> 8;
            int l1 = (int)((wi + 128) & 255) - 128;  wi = (wi - l1) >> 8;
            l2v[j] = (char)wi; l1v[j] = (char)l1; l0v[j] = (char)l0;
        }
        size_t base = (size_t)n * KP + k;
        *(char4*)(Wq + base)         = make_char4(l2v[0], l2v[1], l2v[2], l2v[3]);
        *(char4*)(Wq + base + K)     = make_char4(l1v[0], l1v[1], l1v[2], l1v[3]);
        *(char4*)(Wq + base + 2 * K) = make_char4(l0v[0], l0v[1], l0v[2], l0v[3]);
    }
}

// ---------------- prep: conv_in (blocks 0..127) + quant W0 (blocks 128..159) ----------------
__global__ __launch_bounds__(NTHR)
void prep_kernel(const float* __restrict__ in, int8_t* __restrict__ A,
                 const float* __restrict__ W0, int8_t* __restrict__ W0q)
{
    const int bid = blockIdx.x;
    const int tid = threadIdx.x;
    if (bid >= 128) {                 // quant W0: 32 blocks
        quant_range(W0, W0q, HH, DIN, bid - 128, 32);
        return;
    }
    // conv: in[b][k][t] fp32 -> A[(b*16+t)][k] int8, coalesced
    __shared__ int8_t sbuf[DIN * TT]; // [k][t] layout, 16KB
    const int b = bid;
    const float4* src = (const float4*)(in + (size_t)b * DIN * TT);
    uint32_t* sb32 = (uint32_t*)sbuf;
#pragma unroll
    for (int r = 0; r < 8; ++r) {
        int j = tid + r * NTHR;       // j < 4096; k = j>>2, t0 = (j&3)*4
        float4 v = src[j];
        uint32_t pk = (v.x > 0.5f ? 1u : 0u)
                    | (v.y > 0.5f ? 1u : 0u) << 8
                    | (v.z > 0.5f ? 1u : 0u) << 16
                    | (v.w > 0.5f ? 1u : 0u) << 24;
        sb32[j] = pk;                 // byte addr = k*16 + t0 = 4j
    }
    __syncthreads();
#pragma unroll
    for (int u = tid; u < TT * (DIN / 16); u += NTHR) {
        int t = u >> 6, kseg = u & 63;
        uint32_t w[4];
#pragma unroll
        for (int q = 0; q < 4; ++q) {
            uint32_t b0 = (uint8_t)sbuf[(kseg * 16 + q * 4 + 0) * 16 + t];
            uint32_t b1 = (uint8_t)sbuf[(kseg * 16 + q * 4 + 1) * 16 + t];
            uint32_t b2 = (uint8_t)sbuf[(kseg * 16 + q * 4 + 2) * 16 + t];
            uint32_t b3 = (uint8_t)sbuf[(kseg * 16 + q * 4 + 3) * 16 + t];
            w[q] = b0 | (b1 << 8) | (b2 << 16) | (b3 << 24);
        }
        *(uint4*)(A + ((size_t)b * TT + t) * DIN + kseg * 16) =
            make_uint4(w[0], w[1], w[2], w[3]);
    }
}

// ---------------- fused exact-GEMM (s8 IMMA, 64x64 tile, occ 2) + BN + LIF ----------------
// Extra trailing blocks (bid >= ntiles) perform weight quantization for later layers.
template<bool FINAL>
__global__ __launch_bounds__(NTHR, 2)
void gemm_lif(const int8_t* __restrict__ A,
              const int8_t* __restrict__ Wq,
              const float* __restrict__ bias, const float* __restrict__ gamma,
              const float* __restrict__ beta, const float* __restrict__ mmean,
              const float* __restrict__ mvar,
              int8_t* __restrict__ spk, float* __restrict__ out,
              int K, int N, int ntiles, int gx,
              const float* qsrc1, int8_t* qdst1, int qN1, int qK1, int qblk1,
              const float* qsrc2, int8_t* qdst2, int qN2, int qK2, int qblk2)
{
    const int bid = blockIdx.x;
    const int tid = threadIdx.x;

    if (bid >= ntiles) {              // folded weight-quant blocks (ragged-tail fill)
        int e = bid - ntiles;
        if (e < qblk1) quant_range(qsrc1, qdst1, qN1, qK1, e, qblk1);
        else           quant_range(qsrc2, qdst2, qN2, qK2, e - qblk1, qblk2);
        return;
    }

    const int KP  = 3 * K;
    const int nsc = K / KCB;
    const int m0  = (bid / gx) * TILE;
    const int n0  = (bid % gx) * TILE;

    extern __shared__ __align__(16) char dsm[];
    char* sm = (char*)(((uintptr_t)dsm + 1023) & ~(uintptr_t)1023);
    const uint32_t sm32 = smem_u32(sm);

    const int wid   = tid >> 5;
    const int lane  = tid & 31;
    const int warpM = wid & 3;        // 4 M-groups of 16
    const int warpN = wid >> 2;       // 4 N-groups of 16

    int acc[3][2][4];
#pragma unroll
    for (int p = 0; p < 3; ++p)
#pragma unroll
        for (int j = 0; j < 2; ++j)
#pragma unroll
            for (int q = 0; q < 4; ++q) acc[p][j][q] = 0;

    const int8_t* gA = A  + (size_t)m0 * K;
    const int8_t* gB = Wq + (size_t)n0 * KP;

    auto load_chunk = [&](int c) {
        const uint32_t sbase = sm32 + (uint32_t)(c % 3) * STAGEB;
        const int koff = c * KCB;
#pragma unroll
        for (int u = tid; u < 2048; u += NTHR) {
            if (u < 512) {
                int r = u >> 3, q = u & 7;
                cp16(sbase + SWZ((uint32_t)(r * 128 + q * 16)),
                     gA + (size_t)r * K + koff + q * 16);
            } else {
                int v = u - 512;
                int p = v >> 9, r = (v >> 3) & 63, q = v & 7;
                cp16(sbase + 8192 + (uint32_t)p * 8192 + SWZ((uint32_t)(r * 128 + q * 16)),
                     gB + (size_t)p * K + (size_t)r * KP + koff + q * 16);
            }
        }
    };

    load_chunk(0); CP_COMMIT();
    load_chunk(1); CP_COMMIT();

    const uint32_t aRowByte = (uint32_t)((warpM * 16 + (lane & 7) + ((lane >> 3) & 1) * 8) * 128);
    const uint32_t aCol     = (uint32_t)(((lane >> 4) & 1) * 16);
    const uint32_t bRowByte = (uint32_t)((warpN * 16 + (lane & 7) + ((lane >> 4) & 1) * 8) * 128);
    const uint32_t bCol     = (uint32_t)(((lane >> 3) & 1) * 16);

    for (int i = 0; i < nsc; ++i) {
        CP_WAIT(1);
        __syncthreads();

        if (i + 2 < nsc) load_chunk(i + 2);
        CP_COMMIT();

        const uint32_t sA = sm32 + (uint32_t)(i % 3) * STAGEB;
        const uint32_t sB = sA + 8192;

#pragma unroll
        for (int ks = 0; ks < 4; ++ks) {
            const uint32_t kb = (uint32_t)(ks * 32);
            uint32_t a[4];
            ldsm4(a[0], a[1], a[2], a[3], sA + SWZ(aRowByte + aCol + kb));
#pragma unroll
            for (int p = 0; p < 3; ++p) {
                uint32_t b[4];
                ldsm4(b[0], b[1], b[2], b[3],
                      sB + (uint32_t)p * 8192 + SWZ(bRowByte + bCol + kb));
                imma(acc[p][0], a, b[0], b[1]);
                imma(acc[p][1], a, b[2], b[3]);
            }
        }
    }

    CP_WAIT(0);
    __syncthreads();   // stage buffers reusable as scratch

    // ---- exact recombine: X = (l2*2^16 + l1*2^8 + l0) * 2^-27, single fp32 rounding ----
    float* scrF = (float*)sm;                          // [64][68]
    const double SL = 7.450580596923828125e-9;         // 2^-27
    const int rw = warpM * 16 + (lane >> 2);
    const int cw = warpN * 16 + (lane & 3) * 2;
#pragma unroll
    for (int nf = 0; nf < 2; ++nf) {
        float x[4];
#pragma unroll
        for (int q = 0; q < 4; ++q) {
            double s = (double)acc[0][nf][q] * 65536.0
                     + (double)acc[1][nf][q] * 256.0
                     + (double)acc[2][nf][q];
            x[q] = (float)(s * SL);
        }
        int c = cw + nf * 8;
        *(float2*)&scrF[rw * 68 + c]       = make_float2(x[0], x[1]);
        *(float2*)&scrF[(rw + 8) * 68 + c] = make_float2(x[2], x[3]);
    }
    __syncthreads();

    // ---- BN + LIF (exact elementwise ops) ----
    int8_t* scrS = (int8_t*)(sm + 20480);              // [64][80]
    if (tid < 256) {
        const int col = tid & 63;
        const int bb  = tid >> 6;                      // 4 b-blocks of 16 t
        const int n   = n0 + col;

        const float bo  = bias[n];
        const float ga  = gamma[n];
        const float be  = beta[n];
        const float mu  = mmean[n];
        const float var = mvar[n];
        const float den = sqrtf(__fadd_rn(var, 1e-5f));

        float v = 0.0f, sp = 0.0f, cnt = 0.0f;
#pragma unroll
        for (int t = 0; t < TT; ++t) {
            float x  = scrF[(bb * 16 + t) * 68 + col];
            float u  = __fsub_rn(__fadd_rn(x, bo), mu);
            float xn = __fadd_rn(__fdiv_rn(__fmul_rn(ga, u), den), be);
            v  = __fadd_rn(__fmul_rn(__fmul_rn(v, __fsub_rn(1.0f, sp)), 0.75f), xn);
            sp = (v > 0.5f) ? 1.0f : 0.0f;
            if (FINAL) cnt += sp;
            else       scrS[(bb * 16 + t) * 80 + col] = (int8_t)sp;
        }
        if (FINAL) {
            int bg = (m0 >> 4) + bb;
            out[(size_t)bg * N + n] = cnt * 0.0625f;
        }
    }

    if (!FINAL) {
        __syncthreads();
        if (tid < 256) {               // 64 rows x 64B, uint4 coalesced
            int r = tid >> 2, seg = tid & 3;
            uint4 val = *(const uint4*)(scrS + r * 80 + seg * 16);
            *(uint4*)(spk + (size_t)(m0 + r) * N + n0 + seg * 16) = val;
        }
    }
}

// ---------------- host ----------------
extern "C" void kernel_launch(void* const* d_in, const int* in_sizes, int n_in,
                              void* d_out, int out_size)
{
    const float* spk_in = (const float*)d_in[0];
    const float* W0  = (const float*)d_in[1];
    const float* b0  = (const float*)d_in[2];
    const float* g0  = (const float*)d_in[3];
    const float* be0 = (const float*)d_in[4];
    const float* mm0 = (const float*)d_in[5];
    const float* mv0 = (const float*)d_in[6];
    const float* W1  = (const float*)d_in[7];
    const float* b1  = (const float*)d_in[8];
    const float* g1  = (const float*)d_in[9];
    const float* be1 = (const float*)d_in[10];
    const float* mm1 = (const float*)d_in[11];
    const float* mv1 = (const float*)d_in[12];
    const float* Wo  = (const float*)d_in[13];
    const float* bo  = (const float*)d_in[14];
    const float* go  = (const float*)d_in[15];
    const float* beo = (const float*)d_in[16];
    const float* mmo = (const float*)d_in[17];
    const float* mvo = (const float*)d_in[18];
    float* out = (float*)d_out;

    int8_t *A0, *s0, *s1, *W0q, *W1q, *Woq;
    cudaGetSymbolAddress((void**)&A0,  g_A0);
    cudaGetSymbolAddress((void**)&s0,  g_s0);
    cudaGetSymbolAddress((void**)&s1,  g_s1);
    cudaGetSymbolAddress((void**)&W0q, g_W0q);
    cudaGetSymbolAddress((void**)&W1q, g_W1q);
    cudaGetSymbolAddress((void**)&Woq, g_Woq);

    const int SMEM = 3 * STAGEB + 1024;   // 99328
    cudaFuncSetAttribute((const void*)gemm_lif<false>,
                         cudaFuncAttributeMaxDynamicSharedMemorySize, SMEM);
    cudaFuncSetAttribute((const void*)gemm_lif<true>,
                         cudaFuncAttributeMaxDynamicSharedMemorySize, SMEM);

    // prep: conv_in (128 blocks) + quant W0 (32 blocks)
    prep_kernel<<<160, NTHR>>>(spk_in, A0, W0, W0q);

    // Layer 0: K=1024, N=2048; 1024 tiles + 96 quant blocks (W1q, Woq) in the tail
    {
        int gx = HH / TILE, ntiles = gx * (MTOT / TILE);     // 32 x 32 = 1024
        gemm_lif<false><<<ntiles + 96, NTHR, SMEM>>>(
            A0, W0q, b0, g0, be0, mm0, mv0, s0, nullptr, DIN, HH, ntiles, gx,
            W1, W1q, HH, HH, 64,
            Wo, Woq, DOUT, HH, 32);
    }
    // Layer 1: K=2048, N=2048
    {
        int gx = HH / TILE, ntiles = gx * (MTOT / TILE);     // 1024
        gemm_lif<false><<<ntiles, NTHR, SMEM>>>(
            s0, W1q, b1, g1, be1, mm1, mv1, s1, nullptr, HH, HH, ntiles, gx,
            nullptr, nullptr, 0, 1, 0, nullptr, nullptr, 0, 1, 0);
    }
    // Layer 2: K=2048, N=1024, final
    {
        int gx = DOUT / TILE, ntiles = gx * (MTOT / TILE);   // 16 x 32 = 512
        gemm_lif<true><<<ntiles, NTHR, SMEM>>>(
            s1, Woq, bo, go, beo, mmo, mvo, nullptr, out, HH, DOUT, ntiles, gx,
            nullptr, nullptr, 0, 1, 0, nullptr, nullptr, 0, 1, 0);
    }
}